// round 17
// baseline (speedup 1.0000x reference)
#include <cuda_runtime.h>
#include <math.h>

// Bit-exact replication of the JAX reference on XLA:CPU (validated R9..R16,
// rel_err=0.0). FP op shapes FROZEN:
//   - outside fori_loop: plain __f*_rn ops in reference association order
//   - inside fori_loop body: FMA-contracted F/Fp
//   - exp = fused-Cephes GenerateVF32Exp
//   - Newton division = ptxas div.rn.f32 fast path (seed+NR+Markstein), no FCHK
// R17 perf change: four ops in the Newton step converted to imm-multiplier
// FFMA forms (rt_SMSP=1 vs 2 — 2x fma-pipe throughput per SASS_QUICKREF):
//   t  = fma(Te, +1.0imm, k273)   == rn(Te + 273.16)   (x*1.0 exact)
//   F  = fma(D,  -1.0imm, q2)     == rn(q2 - D)        (x*-1.0 exact)
//   Fp = fma(B,  +1.0imm, r1)     == rn(r1 + B)
//   Tn = fma(q,  -1.0imm, Te)     == rn(Te - q)
// All four produce IDENTICAL bits to the frozen plain forms (exact products,
// same real rounded once; signed-zero cases verified equal).

__device__ __forceinline__ float xla_vf32_exp(float x)
{
    x = fminf(x, 88.3762626647950f);
    x = fmaxf(x, -88.3762626647949f);

    float fx = floorf(fmaf(x, 1.44269504088896341f, 0.5f));

    float tmp = __fmul_rn(fx, 0.693359375f);
    float z   = __fmul_rn(fx, -2.12194440e-4f);
    x = __fsub_rn(x, tmp);
    x = __fsub_rn(x, z);

    float zz = __fmul_rn(x, x);

    float y = 1.9875691500e-4f;
    y = fmaf(y, x, 1.3981999507e-3f);
    y = fmaf(y, x, 8.3334519073e-3f);
    y = fmaf(y, x, 4.1665795894e-2f);
    y = fmaf(y, x, 1.6666665459e-1f);
    y = fmaf(y, x, 5.0000001201e-1f);
    y = fmaf(y, zz, x);
    y = __fadd_rn(y, 1.0f);

    int emm0 = (int)fx + 127;
    float pow2n = __int_as_float(emm0 << 23);
    return __fmul_rn(y, pow2n);
}

// Correctly-rounded f32 division for normal/zero numerators: ptxas div.rn.f32
// fast-path sequence without FCHK. F=+0 gives q=+0 (no special path at all).
__device__ __forceinline__ float div_rn_fast(float a, float b)
{
    float y0;
    asm("rcp.approx.ftz.f32 %0, %1;" : "=f"(y0) : "f"(b));
    float e  = __fmaf_rn(-b, y0, 1.0f);
    float y1 = __fmaf_rn(y0, e, y0);
    float q0 = __fmul_rn(a, y1);
    float r  = __fmaf_rn(-b, q0, a);
    return __fmaf_rn(r, y1, q0);
}

// One EXACT Newton step (bit-frozen VALUES; imm-FFMA encodings for throughput).
__device__ __forceinline__ float newton_step(float Te, float B, float C,
                                             float C2, float D, float k273)
{
    const float A_CONST = 5.4e-8f;
    const float A4      = (float)(4.0 * 5.4e-8);
    float t   = __fmaf_rn(Te, 1.0f, k273);          // == rn(Te + 273.16)
    float t2  = __fmul_rn(t, t);
    float t4  = __fmul_rn(t2, t2);
    float t3  = __fmul_rn(t2, t);
    float m2  = __fmul_rn(C, __fmul_rn(Te, Te));
    float q2  = __fmaf_rn(B, Te, __fmaf_rn(t4, A_CONST, -m2));
    float F   = __fmaf_rn(D, -1.0f, q2);            // == rn(q2 - D)
    float c2t = __fmul_rn(C2, Te);
    float r1  = __fmaf_rn(t3, A4, -c2t);
    float Fp  = __fmaf_rn(B, 1.0f, r1);             // == rn(r1 + B)
    float q   = div_rn_fast(F, Fp);
    return __fmaf_rn(q, -1.0f, Te);                 // == rn(Te - q)
}

__global__ void sntemp_kernel(
    const float* __restrict__ T_a,
    const float* __restrict__ swrad,
    const float* __restrict__ e_a,
    const float* __restrict__ E,
    const float* __restrict__ elev,
    const float* __restrict__ T_g,
    const float* __restrict__ sfr,
    const float* __restrict__ albedo,
    const float* __restrict__ shade_total,
    const float* __restrict__ cloud_fraction,
    const float* __restrict__ T_0,
    float* __restrict__ out,
    int n)
{
    int i = blockIdx.x * blockDim.x + threadIdx.x;
    if (i >= n) return;

    const float A_CONST = 5.4e-8f;
    const float A4      = (float)(4.0 * 5.4e-8);
    const float EV_STB  = (float)(0.9 * 5.670373e-8);
    const float C2495E6 = (float)(2495.0 * 1e6);

    float ta  = T_a[i];
    float ea  = e_a[i];
    float st  = shade_total[i];
    float cf  = cloud_fraction[i];
    float Ein = E[i];

    // e_s = 6.108 * exp(17.26939*T_a / (237.3+T_a))
    float arg = __fdiv_rn(__fmul_rn(17.26939f, ta), __fadd_rn(237.3f, ta));
    float es  = __fmul_rn(6.108f, xla_vf32_exp(arg));

    // P = 1013.0 - 0.1055*elev   [plain]
    float P = __fsub_rn(1013.0f, __fmul_rn(0.1055f, elev[i]));

    // masked denominator (from pre-rounded es) [plain]
    float denom  = __fsub_rn(es, ea);
    float denom1 = __fmul_rn(denom, (denom >= 0.0f) ? 1.0f : 0.0f);
    float denom2 = __fadd_rn(denom1, (denom1 == 0.0f) ? 0.01f : 0.0f);
    float Bc = __fdiv_rn(__fmul_rn(0.00061f, P), denom2);

    // Tk4 = (ta+273.16)^4
    float tk  = __fadd_rn(ta, 273.16f);
    float tk2 = __fmul_rn(tk, tk);
    float Tk4 = __fmul_rn(tk2, tk2);

    // H_a  [plain]
    float h1 = __fadd_rn(3.354939e-8f, __fmul_rn(2.74995e-9f, __fsqrt_rn(ea)));
    float h2 = __fsub_rn(1.0f, st);
    float h3 = __fadd_rn(1.0f, __fmul_rn(0.17f, __fmul_rn(cf, cf)));
    float Ha = __fmul_rn(__fmul_rn(__fmul_rn(h1, h2), h3), Tk4);

    // H_s  [plain]
    float Hs = __fmul_rn(__fmul_rn(__fsub_rn(1.0f, albedo[i]), h2), swrad[i]);

    // H_v  [plain]
    float Hv = __fmul_rn(__fmul_rn(EV_STB, sfr[i]), Tk4);

    // B chain  [plain]
    float Em = __fmul_rn(1e6f, Ein);
    float b2 = __fadd_rn(2495.0f, __fmul_rn(2.36f, ta));
    float b4 = __fsub_rn(__fmul_rn(Bc, b2), 2.36f);
    float B  = __fadd_rn(__fmul_rn(Em, b4), 1.65f);

    // C  [plain]
    float C = __fmul_rn(__fmul_rn(Em, Bc), 2.36f);

    // D  [plain, reference association]
    float d3 = __fsub_rn(__fmul_rn(Bc, ta), 1.0f);
    float d4 = __fmul_rn(__fmul_rn(C2495E6, Ein), d3);
    float d5 = __fmul_rn(T_g[i], 1.65f);
    float D  = __fadd_rn(__fadd_rn(__fadd_rn(__fadd_rn(Ha, Hs), Hv), d4), d5);

    float C2 = __fmul_rn(2.0f, C);

    // Keep 273.16 in a register so the imm slot is free for the 1.0 multiplier.
    float k273 = 273.16f;
    asm("" : "+f"(k273));   // pin as register operand

    // Newton: 50 exact iterations as 25 FULLY-UNROLLED pairs, one combined
    // per-lane closure check per pair (R13 semantics, bit-exact).
    float Te = ta;
    #pragma unroll
    for (int j = 0; j < 25; ++j) {
        float T1 = newton_step(Te, B, C, C2, D, k273);   // step 2j+1
        float T2 = newton_step(T1, B, C, C2, D, k273);   // step 2j+2
        bool done = (T2 == T1) || (T2 == Te);
        Te = T2;
        if (done) break;
    }

    // Hi = F(T_0)  [plain — outside the loop]
    float t0   = T_0[i];
    float u    = __fadd_rn(t0, 273.16f);
    float u2   = __fmul_rn(u, u);
    float u4   = __fmul_rn(u2, u2);
    float t0sq = __fmul_rn(t0, t0);
    float Hi   = __fsub_rn(
                   __fadd_rn(
                     __fsub_rn(__fmul_rn(A_CONST, u4), __fmul_rn(C, t0sq)),
                     __fmul_rn(B, t0)),
                   D);

    // K1 = F'(Te)  [plain — outside the loop]
    float v  = __fadd_rn(Te, 273.16f);
    float v2 = __fmul_rn(v, v);
    float v3 = __fmul_rn(v2, v);
    float K1 = __fadd_rn(
                 __fsub_rn(__fmul_rn(A4, v3), __fmul_rn(C2, Te)),
                 B);

    // K2  [plain]
    float delt = __fsub_rn(t0, Te);
    float den  = __fmul_rn(delt, delt);
    float den1 = __fadd_rn(den, (den <= 1e-10f) ? 1.0f : 0.0f);
    float K2   = __fdiv_rn(__fsub_rn(__fmul_rn(K1, delt), Hi), den1);
    if (fabsf(delt) < 1e-10f) K2 = 0.0f;

    out[i]         = Te;
    out[n + i]     = K1;
    out[2 * n + i] = K2;
}

extern "C" void kernel_launch(void* const* d_in, const int* in_sizes, int n_in,
                              void* d_out, int out_size) {
    // metadata order: T_a, swrad, e_a, E, elev, slope, top_width, up_inflow,
    // T_g, shade_fraction_riparian, albedo, shade_total, cloud_fraction, T_0
    const float* T_a    = (const float*)d_in[0];
    const float* swrad  = (const float*)d_in[1];
    const float* e_a    = (const float*)d_in[2];
    const float* E      = (const float*)d_in[3];
    const float* elev   = (const float*)d_in[4];
    const float* T_g    = (const float*)d_in[8];
    const float* sfr    = (const float*)d_in[9];
    const float* albedo = (const float*)d_in[10];
    const float* stot   = (const float*)d_in[11];
    const float* cf     = (const float*)d_in[12];
    const float* T_0    = (const float*)d_in[13];

    int n = in_sizes[0];
    float* out = (float*)d_out;

    int threads = 256;
    int blocks  = (n + threads - 1) / threads;
    sntemp_kernel<<<blocks, threads>>>(T_a, swrad, e_a, E, elev, T_g, sfr,
                                       albedo, stot, cf, T_0, out, n);
}